// round 2
// baseline (speedup 1.0000x reference)
#include <cuda_runtime.h>
#include <math.h>
#include <stdint.h>

#define DD   4096
#define NT   256
#define NV4  4          // float4 iterations per thread
#define VPT  16         // values per thread

__device__ float g_rstd[DD];
__device__ float g_scal[8];  // 0:tau 1:beta_up 2:gamma 3:beta_fam 4:inv_norm_e

__device__ __forceinline__ float ftanh_fast(float v) {
    float e = __expf(2.0f * v);
    return 1.0f - __fdividef(2.0f, e + 1.0f);
}

__global__ void prep_kernel(const float* __restrict__ ema_mean,
                            const float* __restrict__ ema_sq,
                            const float* __restrict__ ema_out,
                            const float* __restrict__ p_lt,
                            const float* __restrict__ p_lbu,
                            const float* __restrict__ p_lg,
                            const float* __restrict__ p_lbf) {
    __shared__ float sp[NT / 32];
    int tid = threadIdx.x;
    float acc = 0.0f;
    for (int i = tid; i < DD; i += NT) {
        float m = ema_mean[i];
        float v = fmaxf(ema_sq[i] - m * m, 1e-4f);
        g_rstd[i] = 1.0f / (sqrtf(v) + 1e-5f);
        float e = ema_out[i];
        acc = fmaf(e, e, acc);
    }
    #pragma unroll
    for (int o = 16; o; o >>= 1) acc += __shfl_xor_sync(0xffffffffu, acc, o);
    if ((tid & 31) == 0) sp[tid >> 5] = acc;
    __syncthreads();
    if (tid == 0) {
        float s = 0.0f;
        #pragma unroll
        for (int w = 0; w < NT / 32; w++) s += sp[w];
        g_scal[0] = expf(p_lt[0]);                        // tau
        g_scal[1] = log1pf(expf(p_lbu[0]));               // beta_up (softplus)
        g_scal[2] = log1pf(expf(p_lg[0]));                // gamma (softplus)
        g_scal[3] = 1.0f / (1.0f + expf(-p_lbf[0]));      // beta_fam (sigmoid)
        g_scal[4] = 1.0f / fmaxf(sqrtf(s), 1e-12f);       // 1/||ema_out||
    }
}

// descending insert into t0>=t1>=t2>=t3
#define INS_TOP(az) do { float _l=(az), _u;                         \
    _u=fmaxf(t0,_l); _l=fminf(t0,_l); t0=_u;                        \
    _u=fmaxf(t1,_l); _l=fminf(t1,_l); t1=_u;                        \
    _u=fmaxf(t2,_l); _l=fminf(t2,_l); t2=_u;                        \
    t3=fmaxf(t3,_l); } while(0)

// ascending insert into b0<=b1<=b2<=b3
#define INS_BOT(az) do { float _l=(az), _u;                         \
    _u=fminf(b0,_l); _l=fmaxf(b0,_l); b0=_u;                        \
    _u=fminf(b1,_l); _l=fmaxf(b1,_l); b1=_u;                        \
    _u=fminf(b2,_l); _l=fmaxf(b2,_l); b2=_u;                        \
    b3=fminf(b3,_l); } while(0)

#define PROC(J, XX, MM, RR, EE) do {                                \
    float zz = ((XX) - (MM)) * (RR);                                \
    float x2 = (XX) * (XX);                                         \
    float u  = (XX) * fmaf(x2, C1, C0);                             \
    float th = ftanh_fast(u);                                       \
    float hx = 0.5f * (XX);                                         \
    float gg = fmaf(hx, th, hx);                                    \
    s2 = fmaf(gg, gg, s2);                                          \
    sd = fmaf(gg, (EE), sd);                                        \
    float az = fabsf(zz);                                           \
    INS_TOP(az);                                                    \
    INS_BOT(az);                                                    \
    gbuf[J] = gg; zbuf[J] = zz;                                     \
} while(0)

// descending insert into 8-deep sorted list r0..r7
#define INS8_TOP(v) do { float _l=(v), _u;                          \
    _u=fmaxf(r0,_l); _l=fminf(r0,_l); r0=_u;                        \
    _u=fmaxf(r1,_l); _l=fminf(r1,_l); r1=_u;                        \
    _u=fmaxf(r2,_l); _l=fminf(r2,_l); r2=_u;                        \
    _u=fmaxf(r3,_l); _l=fminf(r3,_l); r3=_u;                        \
    _u=fmaxf(r4,_l); _l=fminf(r4,_l); r4=_u;                        \
    _u=fmaxf(r5,_l); _l=fminf(r5,_l); r5=_u;                        \
    _u=fmaxf(r6,_l); _l=fminf(r6,_l); r6=_u;                        \
    r7=fmaxf(r7,_l); } while(0)

#define INS8_BOT(v) do { float _l=(v), _u;                          \
    _u=fminf(r0,_l); _l=fmaxf(r0,_l); r0=_u;                        \
    _u=fminf(r1,_l); _l=fmaxf(r1,_l); r1=_u;                        \
    _u=fminf(r2,_l); _l=fmaxf(r2,_l); r2=_u;                        \
    _u=fminf(r3,_l); _l=fmaxf(r3,_l); r3=_u;                        \
    _u=fminf(r4,_l); _l=fmaxf(r4,_l); r4=_u;                        \
    _u=fminf(r5,_l); _l=fmaxf(r5,_l); r5=_u;                        \
    _u=fminf(r6,_l); _l=fmaxf(r6,_l); r6=_u;                        \
    r7=fminf(r7,_l); } while(0)

__global__ __launch_bounds__(NT)
void gelu_gate_kernel(const float* __restrict__ x,
                      const float* __restrict__ ema_mean,
                      const float* __restrict__ ema_out,
                      float* __restrict__ out) {
    __shared__ float s_top[NT * 4];
    __shared__ float s_bot[NT * 4];
    __shared__ float s_part[2 * (NT / 32)];
    __shared__ float s_res[8];   // 0:v16 1:w16 2:gate_cos 3:bu 4:gm 5:bf

    const int   row = blockIdx.x;
    const int   tid = threadIdx.x;
    const float4* xr = reinterpret_cast<const float4*>(x + (size_t)row * DD);
    const float4* mr = reinterpret_cast<const float4*>(ema_mean);
    const float4* rr = reinterpret_cast<const float4*>(g_rstd);
    const float4* er = reinterpret_cast<const float4*>(ema_out);
    float4* orow = reinterpret_cast<float4*>(out + (size_t)row * DD);

    const float C0 = 0.7978845608028654f;
    const float C1 = 0.044715f * 0.7978845608028654f;
    const float INF = __int_as_float(0x7f800000);

    float gbuf[VPT], zbuf[VPT];
    float t0 = -1.f, t1 = -1.f, t2 = -1.f, t3 = -1.f;
    float b0 = INF, b1 = INF, b2 = INF, b3 = INF;
    float s2 = 0.f, sd = 0.f;

    #pragma unroll
    for (int i = 0; i < NV4; i++) {
        int idx = i * NT + tid;
        float4 xv = xr[idx];
        float4 mv = mr[idx];
        float4 rv = rr[idx];
        float4 ev = er[idx];
        PROC(i * 4 + 0, xv.x, mv.x, rv.x, ev.x);
        PROC(i * 4 + 1, xv.y, mv.y, rv.y, ev.y);
        PROC(i * 4 + 2, xv.z, mv.z, rv.z, ev.z);
        PROC(i * 4 + 3, xv.w, mv.w, rv.w, ev.w);
    }

    // block partial sums
    #pragma unroll
    for (int o = 16; o; o >>= 1) {
        s2 += __shfl_xor_sync(0xffffffffu, s2, o);
        sd += __shfl_xor_sync(0xffffffffu, sd, o);
    }
    if ((tid & 31) == 0) {
        s_part[(tid >> 5) * 2 + 0] = s2;
        s_part[(tid >> 5) * 2 + 1] = sd;
    }
    // publish candidates
    s_top[0 * NT + tid] = t0;  s_top[1 * NT + tid] = t1;
    s_top[2 * NT + tid] = t2;  s_top[3 * NT + tid] = t3;
    s_bot[0 * NT + tid] = b0;  s_bot[1 * NT + tid] = b1;
    s_bot[2 * NT + tid] = b2;  s_bot[3 * NT + tid] = b3;
    __syncthreads();

    const int wid = tid >> 5, lane = tid & 31;
    if (wid == 0) {
        // 16th-largest |z| among 1024 candidates
        float r0 = -1.f, r1 = -1.f, r2 = -1.f, r3 = -1.f,
              r4 = -1.f, r5 = -1.f, r6 = -1.f, r7 = -1.f;
        #pragma unroll
        for (int i = 0; i < 32; i++) {
            float v = s_top[lane + 32 * i];
            INS8_TOP(v);
        }
        float last = -1.f;
        #pragma unroll
        for (int it = 0; it < 16; it++) {
            float m = r0;
            #pragma unroll
            for (int o = 16; o; o >>= 1) m = fmaxf(m, __shfl_xor_sync(0xffffffffu, m, o));
            last = m;
            if (r0 == m) { r0=r1; r1=r2; r2=r3; r3=r4; r4=r5; r5=r6; r6=r7; r7=-1.f; }
        }
        if (lane == 0) s_res[0] = last;
    } else if (wid == 1) {
        // 16th-smallest |z| among 1024 candidates
        float r0 = INF, r1 = INF, r2 = INF, r3 = INF,
              r4 = INF, r5 = INF, r6 = INF, r7 = INF;
        #pragma unroll
        for (int i = 0; i < 32; i++) {
            float v = s_bot[lane + 32 * i];
            INS8_BOT(v);
        }
        float last = INF;
        #pragma unroll
        for (int it = 0; it < 16; it++) {
            float m = r0;
            #pragma unroll
            for (int o = 16; o; o >>= 1) m = fminf(m, __shfl_xor_sync(0xffffffffu, m, o));
            last = m;
            if (r0 == m) { r0=r1; r1=r2; r2=r3; r3=r4; r4=r5; r5=r6; r6=r7; r7=INF; }
        }
        if (lane == 0) s_res[1] = last;
    } else if (wid == 2 && lane == 0) {
        float a = 0.f, b = 0.f;
        #pragma unroll
        for (int w = 0; w < NT / 32; w++) { a += s_part[2*w]; b += s_part[2*w+1]; }
        float nrm = fmaxf(sqrtf(a), 1e-12f);
        float cs  = b * g_scal[4] / nrm;
        cs = fminf(fmaxf(cs, -1.0f), 1.0f);
        s_res[2] = expf(-g_scal[0] * cs);
        s_res[3] = g_scal[1];
        s_res[4] = g_scal[2];
        s_res[5] = g_scal[3];
    }
    __syncthreads();

    const float v16 = s_res[0];
    const float w16 = s_res[1];
    const float gc  = s_res[2];
    const float bu  = s_res[3];
    const float gm  = s_res[4];
    const float bf  = s_res[5];

    #pragma unroll
    for (int i = 0; i < NV4; i++) {
        float oa[4];
        #pragma unroll
        for (int c = 0; c < 4; c++) {
            int j = i * 4 + c;
            float gg = gbuf[j];
            float zz = zbuf[j];
            float az = fabsf(zz);
            float gate = 1.0f;
            if (az >= v16) {
                float th = ftanh_fast(gm * zz);
                gate = fminf(fmaxf(fmaf(bu, th, 1.0f), 0.1f), 8.0f);
            }
            if (az <= w16) gate = bf;
            oa[c] = gg * gate * gc;
        }
        float4 ov;
        ov.x = oa[0]; ov.y = oa[1]; ov.z = oa[2]; ov.w = oa[3];
        orow[i * NT + tid] = ov;
    }
}

extern "C" void kernel_launch(void* const* d_in, const int* in_sizes, int n_in,
                              void* d_out, int out_size) {
    const float* x        = (const float*)d_in[0];
    const float* ema_mean = (const float*)d_in[1];
    const float* ema_sq   = (const float*)d_in[2];
    const float* ema_out  = (const float*)d_in[3];
    const float* lt       = (const float*)d_in[4];
    const float* lbu      = (const float*)d_in[5];
    const float* lg       = (const float*)d_in[6];
    const float* lbf      = (const float*)d_in[7];
    float* out = (float*)d_out;

    int rows = in_sizes[0] / DD;
    if (rows < 1) rows = 1;

    prep_kernel<<<1, NT>>>(ema_mean, ema_sq, ema_out, lt, lbu, lg, lbf);
    gelu_gate_kernel<<<rows, NT>>>(x, ema_mean, ema_out, out);
}